// round 5
// baseline (speedup 1.0000x reference)
#include <cuda_runtime.h>
#include <cuda_bf16.h>
#include <cstdint>

#define NMAX 100000
#define EMAX 1600000

// ---------------- device scratch -------------------------------------------
__device__ int   g_cnt[NMAX];
__device__ int   g_cur[NMAX];
__device__ int   g_off[NMAX + 1];
__device__ float g_dinv[NMAX];
__device__ int   g_srcs[EMAX];
__device__ alignas(16) float g_bufA[(size_t)NMAX * 128];
__device__ alignas(16) float g_bufG[(size_t)NMAX * 128];
// transposed weight images [n][k], bf16 hi/lo
__device__ alignas(16) __nv_bfloat16 g_W0h[128 * 128], g_W0l[128 * 128];
__device__ alignas(16) __nv_bfloat16 g_W1h[128 * 128], g_W1l[128 * 128];
__device__ alignas(16) __nv_bfloat16 g_W2h[64 * 128],  g_W2l[64 * 128];

// ---------------- CSR build ------------------------------------------------
__global__ void k_zero(int n) {
    int i = blockIdx.x * blockDim.x + threadIdx.x;
    if (i < n) { g_cnt[i] = 0; g_cur[i] = 0; }
}
__global__ void k_hist(const int* __restrict__ ei, int e, int n) {
    int i = blockIdx.x * blockDim.x + threadIdx.x;
    if (i < e) {
        int d = ei[e + i];
        if ((unsigned)d < (unsigned)n) atomicAdd(&g_cnt[d], 1);
    }
}
__global__ void k_scan(int n) {
    __shared__ int part[1024];
    int t  = threadIdx.x;
    int ch = (n + 1023) >> 10;
    int b  = t * ch;
    int en = min(n, b + ch);
    int s = 0;
    for (int i = b; i < en; i++) s += g_cnt[i];
    part[t] = s;
    __syncthreads();
    for (int off = 1; off < 1024; off <<= 1) {
        int v = (t >= off) ? part[t - off] : 0;
        __syncthreads();
        part[t] += v;
        __syncthreads();
    }
    int ex = (t == 0) ? 0 : part[t - 1];
    for (int i = b; i < en; i++) {
        g_off[i] = ex;
        int c = g_cnt[i];
        ex += c;
        g_dinv[i] = rsqrtf((float)(c + 1));
    }
    if (t == 1023) g_off[n] = part[1023];
}
__global__ void k_fill(const int* __restrict__ ei, int e, int n) {
    int i = blockIdx.x * blockDim.x + threadIdx.x;
    if (i < e) {
        int d = ei[e + i];
        int s = ei[i];
        if ((unsigned)d < (unsigned)n && (unsigned)s < (unsigned)n) {
            int pos = g_off[d] + atomicAdd(&g_cur[d], 1);
            g_srcs[pos] = s;
        }
    }
}

// -------- weight prep: transpose + bf16 hi/lo split, layout [n][k] ---------
template <int NCOL>
__global__ void k_prepW(const float* __restrict__ W, __nv_bfloat16* __restrict__ Bh,
                        __nv_bfloat16* __restrict__ Bl) {
    int idx = blockIdx.x * blockDim.x + threadIdx.x;
    if (idx >= NCOL * 128) return;
    int k = idx / NCOL, nn = idx % NCOL;
    float v = W[k * NCOL + nn];
    __nv_bfloat16 hi = __float2bfloat16(v);
    __nv_bfloat16 lo = __float2bfloat16(v - __bfloat162float(hi));
    Bh[nn * 128 + k] = hi;
    Bl[nn * 128 + k] = lo;
}

// ---------------- mma.sync GEMM: g_bufG = dinv[row] * (X @ W) --------------
// m16n8k16 bf16 HMMA, bf16x3 split (AhBh + AhBl + AlBh).
// CTA: 128 rows, 8 warps = 4 m-groups x 2 n-groups; warp tile 32 x NCOL/2.
__device__ __forceinline__ void mma16816(float* c, const uint32_t* a,
                                         uint32_t b0, uint32_t b1) {
    asm volatile(
        "mma.sync.aligned.m16n8k16.row.col.f32.bf16.bf16.f32 "
        "{%0,%1,%2,%3}, {%4,%5,%6,%7}, {%8,%9}, {%0,%1,%2,%3};"
        : "+f"(c[0]), "+f"(c[1]), "+f"(c[2]), "+f"(c[3])
        : "r"(a[0]), "r"(a[1]), "r"(a[2]), "r"(a[3]), "r"(b0), "r"(b1));
}

template <int NCOL, bool FROM_EXT>
__global__ void __launch_bounds__(256, 1)
k_gemm_mma(const float* __restrict__ Xext, const __nv_bfloat16* __restrict__ Bh,
           const __nv_bfloat16* __restrict__ Bl, int n) {
    constexpr int KP = 136;                 // padded k-stride (272B: conflict-free)
    constexpr int NT = NCOL / 16;           // n-tiles per warp

    extern __shared__ __nv_bfloat16 sm[];
    __nv_bfloat16* As_h = sm;                       // [128][KP]
    __nv_bfloat16* As_l = As_h + 128 * KP;
    __nv_bfloat16* Bs_h = As_l + 128 * KP;          // [NCOL][KP]
    __nv_bfloat16* Bs_l = Bs_h + NCOL * KP;

    int tid  = threadIdx.x;
    int row0 = blockIdx.x * 128;
    const float* X = FROM_EXT ? Xext : (const float*)g_bufA;

    // stage B: uint4 copy from [n][128] global into padded smem rows
    for (int i = tid; i < NCOL * 16; i += 256) {
        int nr = i >> 4, kc = i & 15;      // kc: chunk of 8 bf16 (16B)
        uint4 vh = ((const uint4*)Bh)[(size_t)nr * 16 + kc];
        uint4 vl = ((const uint4*)Bl)[(size_t)nr * 16 + kc];
        *(uint4*)(Bs_h + nr * KP + kc * 8) = vh;
        *(uint4*)(Bs_l + nr * KP + kc * 8) = vl;
    }
    // stage A: fp32 coalesced load, split bf16 hi/lo
    for (int i = tid; i < 128 * 32; i += 256) {
        int row = i >> 5, c4 = i & 31, k = c4 * 4;
        int gr = row0 + row;
        float4 v = (gr < n) ? ((const float4*)X)[(size_t)gr * 32 + c4]
                            : make_float4(0.f, 0.f, 0.f, 0.f);
        __nv_bfloat16 h0 = __float2bfloat16(v.x), h1 = __float2bfloat16(v.y);
        __nv_bfloat16 h2 = __float2bfloat16(v.z), h3 = __float2bfloat16(v.w);
        __nv_bfloat162 hi01(h0, h1), hi23(h2, h3);
        __nv_bfloat162 lo01(__float2bfloat16(v.x - __bfloat162float(h0)),
                            __float2bfloat16(v.y - __bfloat162float(h1)));
        __nv_bfloat162 lo23(__float2bfloat16(v.z - __bfloat162float(h2)),
                            __float2bfloat16(v.w - __bfloat162float(h3)));
        *(__nv_bfloat162*)(As_h + row * KP + k)     = hi01;
        *(__nv_bfloat162*)(As_h + row * KP + k + 2) = hi23;
        *(__nv_bfloat162*)(As_l + row * KP + k)     = lo01;
        *(__nv_bfloat162*)(As_l + row * KP + k + 2) = lo23;
    }
    __syncthreads();

    int wid  = tid >> 5, lane = tid & 31;
    int wm = wid & 3, wn = wid >> 2;
    int row_base = wm * 32;
    int col_base = wn * (NCOL / 2);
    int gid = lane >> 2, tig = lane & 3;

    float acc[2][NT][4];
#pragma unroll
    for (int mt = 0; mt < 2; mt++)
#pragma unroll
        for (int nt = 0; nt < NT; nt++)
#pragma unroll
            for (int q = 0; q < 4; q++) acc[mt][nt][q] = 0.f;

#pragma unroll
    for (int pass = 0; pass < 3; pass++) {
        const __nv_bfloat16* A_s = (pass < 2) ? As_h : As_l;
        const __nv_bfloat16* B_s = (pass == 1) ? Bs_l : Bs_h;
#pragma unroll
        for (int kt = 0; kt < 8; kt++) {
            int ke = kt * 16 + tig * 2;
            uint32_t a[2][4];
#pragma unroll
            for (int mt = 0; mt < 2; mt++) {
                int r = row_base + mt * 16 + gid;
                a[mt][0] = *(const uint32_t*)(A_s + r * KP + ke);
                a[mt][1] = *(const uint32_t*)(A_s + (r + 8) * KP + ke);
                a[mt][2] = *(const uint32_t*)(A_s + r * KP + ke + 8);
                a[mt][3] = *(const uint32_t*)(A_s + (r + 8) * KP + ke + 8);
            }
#pragma unroll
            for (int nt = 0; nt < NT; nt++) {
                int nn = col_base + nt * 8 + gid;
                uint32_t b0 = *(const uint32_t*)(B_s + nn * KP + ke);
                uint32_t b1 = *(const uint32_t*)(B_s + nn * KP + ke + 8);
                mma16816(acc[0][nt], a[0], b0, b1);
                mma16816(acc[1][nt], a[1], b0, b1);
            }
        }
    }

    // epilogue: scale by dinv[row], write fp32
#pragma unroll
    for (int mt = 0; mt < 2; mt++) {
        int r1 = row0 + row_base + mt * 16 + gid;
        int r2 = r1 + 8;
        float dv1 = (r1 < n) ? g_dinv[r1] : 0.f;
        float dv2 = (r2 < n) ? g_dinv[r2] : 0.f;
        float* G1 = g_bufG + (size_t)r1 * NCOL;
        float* G2 = g_bufG + (size_t)r2 * NCOL;
#pragma unroll
        for (int nt = 0; nt < NT; nt++) {
            int col = col_base + nt * 8 + tig * 2;
            if (r1 < n)
                *(float2*)(G1 + col) = make_float2(acc[mt][nt][0] * dv1,
                                                   acc[mt][nt][1] * dv1);
            if (r2 < n)
                *(float2*)(G2 + col) = make_float2(acc[mt][nt][2] * dv2,
                                                   acc[mt][nt][3] * dv2);
        }
    }
}

// ------- Aggregation: out[d] = act(dinv[d]*(G[d] + sum_s G[s]) + b) --------
template <bool RELU>
__global__ void k_agg128(const float* __restrict__ bias, int n) {
    int w = (blockIdx.x * blockDim.x + threadIdx.x) >> 5;
    if (w >= n) return;
    int lane = threadIdx.x & 31;
    const float4* G = (const float4*)g_bufG;

    float4 acc = G[(size_t)w * 32 + lane];
    int beg = g_off[w], end = g_off[w + 1];
    int i = beg;
    for (; i + 2 <= end; i += 2) {
        int s0 = g_srcs[i], s1 = g_srcs[i + 1];
        float4 v0 = G[(size_t)s0 * 32 + lane];
        float4 v1 = G[(size_t)s1 * 32 + lane];
        acc.x += v0.x + v1.x; acc.y += v0.y + v1.y;
        acc.z += v0.z + v1.z; acc.w += v0.w + v1.w;
    }
    if (i < end) {
        int s = g_srcs[i];
        float4 v = G[(size_t)s * 32 + lane];
        acc.x += v.x; acc.y += v.y; acc.z += v.z; acc.w += v.w;
    }
    float dv = g_dinv[w];
    float4 bb = ((const float4*)bias)[lane];
    float4 o = make_float4(acc.x * dv + bb.x, acc.y * dv + bb.y,
                           acc.z * dv + bb.z, acc.w * dv + bb.w);
    if (RELU) {
        o.x = fmaxf(o.x, 0.f); o.y = fmaxf(o.y, 0.f);
        o.z = fmaxf(o.z, 0.f); o.w = fmaxf(o.w, 0.f);
    }
    ((float4*)g_bufA)[(size_t)w * 32 + lane] = o;
}

__global__ void k_agg64(const float* __restrict__ bias, float* __restrict__ O, int n) {
    int w = (blockIdx.x * blockDim.x + threadIdx.x) >> 5;
    if (w >= n) return;
    int lane = threadIdx.x & 31;
    const float2* G = (const float2*)g_bufG;

    float2 acc = G[(size_t)w * 32 + lane];
    int beg = g_off[w], end = g_off[w + 1];
    int i = beg;
    for (; i + 2 <= end; i += 2) {
        int s0 = g_srcs[i], s1 = g_srcs[i + 1];
        float2 v0 = G[(size_t)s0 * 32 + lane];
        float2 v1 = G[(size_t)s1 * 32 + lane];
        acc.x += v0.x + v1.x; acc.y += v0.y + v1.y;
    }
    if (i < end) {
        int s = g_srcs[i];
        float2 v = G[(size_t)s * 32 + lane];
        acc.x += v.x; acc.y += v.y;
    }
    float dv = g_dinv[w];
    float2 bb = ((const float2*)bias)[lane];
    float2 o = make_float2(acc.x * dv + bb.x, acc.y * dv + bb.y);
    ((float2*)O)[(size_t)w * 32 + lane] = o;
}

// ---------------- launch ----------------------------------------------------
extern "C" void kernel_launch(void* const* d_in, const int* in_sizes, int n_in,
                              void* d_out, int out_size) {
    const float* x  = (const float*)d_in[0];
    const int*   ei = (const int*)d_in[1];
    const float* W0 = (const float*)d_in[2];
    const float* b0 = (const float*)d_in[3];
    const float* W1 = (const float*)d_in[4];
    const float* b1 = (const float*)d_in[5];
    const float* W2 = (const float*)d_in[6];
    const float* b2 = (const float*)d_in[7];

    int n = in_sizes[0] / 128;   // 100000
    int e = in_sizes[1] / 2;     // 1600000

    constexpr int KP = 136;
    constexpr int SM128 = (2 * 128 * KP + 2 * 128 * KP) * 2;  // 139264 B
    constexpr int SM64  = (2 * 128 * KP + 2 * 64 * KP) * 2;   // 104448 B
    static bool attr_done = false;
    if (!attr_done) {
        cudaFuncSetAttribute(k_gemm_mma<128, true >, cudaFuncAttributeMaxDynamicSharedMemorySize, SM128);
        cudaFuncSetAttribute(k_gemm_mma<128, false>, cudaFuncAttributeMaxDynamicSharedMemorySize, SM128);
        cudaFuncSetAttribute(k_gemm_mma<64,  false>, cudaFuncAttributeMaxDynamicSharedMemorySize, SM64);
        attr_done = true;
    }

    // weight prep
    k_prepW<128><<<(128 * 128 + 255) / 256, 256>>>(W0, g_W0h, g_W0l);
    k_prepW<128><<<(128 * 128 + 255) / 256, 256>>>(W1, g_W1h, g_W1l);
    k_prepW<64><<<(64 * 128 + 255) / 256, 256>>>(W2, g_W2h, g_W2l);

    // CSR build
    k_zero<<<(n + 255) / 256, 256>>>(n);
    k_hist<<<(e + 255) / 256, 256>>>(ei, e, n);
    k_scan<<<1, 1024>>>(n);
    k_fill<<<(e + 255) / 256, 256>>>(ei, e, n);

    int gemmGrid = (n + 127) / 128;
    int aggGrid  = (n + 7) / 8;

    k_gemm_mma<128, true ><<<gemmGrid, 256, SM128>>>(x, g_W0h, g_W0l, n);
    k_agg128<true><<<aggGrid, 256>>>(b0, n);
    k_gemm_mma<128, false><<<gemmGrid, 256, SM128>>>(nullptr, g_W1h, g_W1l, n);
    k_agg128<true><<<aggGrid, 256>>>(b1, n);
    k_gemm_mma<64, false><<<gemmGrid, 256, SM64>>>(nullptr, g_W2h, g_W2l, n);
    k_agg64<<<aggGrid, 256>>>(b2, (float*)d_out, n);
}

// round 6
// speedup vs baseline: 1.3461x; 1.3461x over previous
#include <cuda_runtime.h>
#include <cstdint>

#define NMAX 100000
#define EMAX 1600000

// ---------------- device scratch -------------------------------------------
__device__ int   g_cnt[NMAX];
__device__ int   g_cur[NMAX];
__device__ int   g_off[NMAX + 1];
__device__ float g_dinv[NMAX];
__device__ int   g_srcs[EMAX];
__device__ alignas(16) float g_bufA[(size_t)NMAX * 128];
__device__ alignas(16) float g_bufG[(size_t)NMAX * 128];

// ---------------- f32x2 packed FMA helpers ---------------------------------
__device__ __forceinline__ void fma2(unsigned long long& acc, unsigned long long a,
                                     unsigned long long b) {
    asm("fma.rn.f32x2 %0, %1, %2, %0;" : "+l"(acc) : "l"(a), "l"(b));
}
__device__ __forceinline__ unsigned long long splat2(float v) {
    unsigned long long r;
    uint32_t b = __float_as_uint(v);
    asm("mov.b64 %0, {%1, %1};" : "=l"(r) : "r"(b));
    return r;
}
__device__ __forceinline__ float2 unpack2(unsigned long long v) {
    uint32_t lo, hi;
    asm("mov.b64 {%0, %1}, %2;" : "=r"(lo), "=r"(hi) : "l"(v));
    return make_float2(__uint_as_float(lo), __uint_as_float(hi));
}

// ---------------- CSR build ------------------------------------------------
__global__ void k_zero(int n) {
    int i = blockIdx.x * blockDim.x + threadIdx.x;
    if (i < n) { g_cnt[i] = 0; g_cur[i] = 0; }
}
__global__ void k_hist(const int* __restrict__ ei, int e, int n) {
    int i = blockIdx.x * blockDim.x + threadIdx.x;
    if (i < e) {
        int d = ei[e + i];
        if ((unsigned)d < (unsigned)n) atomicAdd(&g_cnt[d], 1);
    }
}
__global__ void k_scan(int n) {
    __shared__ int part[1024];
    int t  = threadIdx.x;
    int ch = (n + 1023) >> 10;
    int b  = t * ch;
    int en = min(n, b + ch);
    int s = 0;
    for (int i = b; i < en; i++) s += g_cnt[i];
    part[t] = s;
    __syncthreads();
    for (int off = 1; off < 1024; off <<= 1) {
        int v = (t >= off) ? part[t - off] : 0;
        __syncthreads();
        part[t] += v;
        __syncthreads();
    }
    int ex = (t == 0) ? 0 : part[t - 1];
    for (int i = b; i < en; i++) {
        g_off[i] = ex;
        int c = g_cnt[i];
        ex += c;
        g_dinv[i] = rsqrtf((float)(c + 1));
    }
    if (t == 1023) g_off[n] = part[1023];
}
__global__ void k_fill(const int* __restrict__ ei, int e, int n) {
    int i = blockIdx.x * blockDim.x + threadIdx.x;
    if (i < e) {
        int d = ei[e + i];
        int s = ei[i];
        if ((unsigned)d < (unsigned)n && (unsigned)s < (unsigned)n) {
            int pos = g_off[d] + atomicAdd(&g_cur[d], 1);
            g_srcs[pos] = s;
        }
    }
}

// ---------- GEMM (f32x2): g_bufG = dinv[row] * (X @ W) ---------------------
// X: [n,128], W: [128,NCOL] row-major. 256 threads.
// Thread tile: RPT rows x 8 cols (4 f32x2 col-pairs). RPB = 64 rows/block.
template <int NCOL, int RPT, bool FROM_EXT>
__global__ void __launch_bounds__(256)
k_gemm_f2(const float* __restrict__ Xext, const float* __restrict__ W, int n) {
    constexpr int TX  = NCOL / 8;       // threads across cols (16 / 8)
    constexpr int TY  = 256 / TX;       // 16 / 32
    constexpr int RPB = RPT * TY;       // 64 both configs
    constexpr int KC  = 32;             // k chunk

    __shared__ float Xs[RPB * 128];     // 32KB
    __shared__ float Ws[KC * NCOL];     // 16KB / 8KB

    int tid  = threadIdx.x;
    int row0 = blockIdx.x * RPB;
    const float4* Xsrc = FROM_EXT ? (const float4*)Xext : (const float4*)g_bufA;

    // stage X tile
    for (int i = tid; i < RPB * 32; i += 256) {
        int r = i >> 5, c = i & 31;
        int gr = row0 + r;
        float4 v = (gr < n) ? Xsrc[(size_t)gr * 32 + c]
                            : make_float4(0.f, 0.f, 0.f, 0.f);
        ((float4*)Xs)[i] = v;
    }

    int tx = tid % TX, ty = tid / TX;
    int rbase = ty * RPT;

    unsigned long long acc[RPT][4];
#pragma unroll
    for (int r = 0; r < RPT; r++)
#pragma unroll
        for (int p = 0; p < 4; p++) acc[r][p] = 0ull;

    for (int kc = 0; kc < 128; kc += KC) {
        __syncthreads();
        for (int i = tid; i < KC * NCOL / 4; i += 256)
            ((float4*)Ws)[i] = ((const float4*)W)[kc * (NCOL / 4) + i];
        __syncthreads();

#pragma unroll
        for (int k4 = 0; k4 < KC; k4 += 4) {
            float a_[RPT][4];
#pragma unroll
            for (int r = 0; r < RPT; r++) {
                float4 a = ((float4*)Xs)[(rbase + r) * 32 + ((kc + k4) >> 2)];
                a_[r][0] = a.x; a_[r][1] = a.y; a_[r][2] = a.z; a_[r][3] = a.w;
            }
#pragma unroll
            for (int kk = 0; kk < 4; kk++) {
                const float* wr = Ws + (k4 + kk) * NCOL + tx * 8;
                ulonglong2 b01 = *(const ulonglong2*)wr;
                ulonglong2 b23 = *(const ulonglong2*)(wr + 4);
#pragma unroll
                for (int r = 0; r < RPT; r++) {
                    unsigned long long aa = splat2(a_[r][kk]);
                    fma2(acc[r][0], aa, b01.x);
                    fma2(acc[r][1], aa, b01.y);
                    fma2(acc[r][2], aa, b23.x);
                    fma2(acc[r][3], aa, b23.y);
                }
            }
        }
    }

    // epilogue: scale by dinv, write fp32
#pragma unroll
    for (int r = 0; r < RPT; r++) {
        int gr = row0 + rbase + r;
        if (gr < n) {
            float dv = g_dinv[gr];
            float2 p0 = unpack2(acc[r][0]), p1 = unpack2(acc[r][1]);
            float2 p2 = unpack2(acc[r][2]), p3 = unpack2(acc[r][3]);
            float* Gr = g_bufG + (size_t)gr * NCOL + tx * 8;
            *(float4*)Gr       = make_float4(p0.x * dv, p0.y * dv, p1.x * dv, p1.y * dv);
            *(float4*)(Gr + 4) = make_float4(p2.x * dv, p2.y * dv, p3.x * dv, p3.y * dv);
        }
    }
}

// ------- Aggregation: out[d] = act(dinv[d]*(G[d] + sum_s G[s]) + b) --------
template <bool RELU>
__global__ void k_agg128(const float* __restrict__ bias, int n) {
    int w = (blockIdx.x * blockDim.x + threadIdx.x) >> 5;
    if (w >= n) return;
    int lane = threadIdx.x & 31;
    const float4* G = (const float4*)g_bufG;

    float4 acc = G[(size_t)w * 32 + lane];
    int beg = g_off[w], end = g_off[w + 1];
    int i = beg;
    for (; i + 2 <= end; i += 2) {
        int s0 = g_srcs[i], s1 = g_srcs[i + 1];
        float4 v0 = G[(size_t)s0 * 32 + lane];
        float4 v1 = G[(size_t)s1 * 32 + lane];
        acc.x += v0.x + v1.x; acc.y += v0.y + v1.y;
        acc.z += v0.z + v1.z; acc.w += v0.w + v1.w;
    }
    if (i < end) {
        int s = g_srcs[i];
        float4 v = G[(size_t)s * 32 + lane];
        acc.x += v.x; acc.y += v.y; acc.z += v.z; acc.w += v.w;
    }
    float dv = g_dinv[w];
    float4 bb = ((const float4*)bias)[lane];
    float4 o = make_float4(acc.x * dv + bb.x, acc.y * dv + bb.y,
                           acc.z * dv + bb.z, acc.w * dv + bb.w);
    if (RELU) {
        o.x = fmaxf(o.x, 0.f); o.y = fmaxf(o.y, 0.f);
        o.z = fmaxf(o.z, 0.f); o.w = fmaxf(o.w, 0.f);
    }
    ((float4*)g_bufA)[(size_t)w * 32 + lane] = o;
}

__global__ void k_agg64(const float* __restrict__ bias, float* __restrict__ O, int n) {
    int w = (blockIdx.x * blockDim.x + threadIdx.x) >> 5;
    if (w >= n) return;
    int lane = threadIdx.x & 31;
    const float2* G = (const float2*)g_bufG;

    float2 acc = G[(size_t)w * 32 + lane];
    int beg = g_off[w], end = g_off[w + 1];
    int i = beg;
    for (; i + 2 <= end; i += 2) {
        int s0 = g_srcs[i], s1 = g_srcs[i + 1];
        float2 v0 = G[(size_t)s0 * 32 + lane];
        float2 v1 = G[(size_t)s1 * 32 + lane];
        acc.x += v0.x + v1.x; acc.y += v0.y + v1.y;
    }
    if (i < end) {
        int s = g_srcs[i];
        float2 v = G[(size_t)s * 32 + lane];
        acc.x += v.x; acc.y += v.y;
    }
    float dv = g_dinv[w];
    float2 bb = ((const float2*)bias)[lane];
    float2 o = make_float2(acc.x * dv + bb.x, acc.y * dv + bb.y);
    ((float2*)O)[(size_t)w * 32 + lane] = o;
}

// ---------------- launch ----------------------------------------------------
extern "C" void kernel_launch(void* const* d_in, const int* in_sizes, int n_in,
                              void* d_out, int out_size) {
    const float* x  = (const float*)d_in[0];
    const int*   ei = (const int*)d_in[1];
    const float* W0 = (const float*)d_in[2];
    const float* b0 = (const float*)d_in[3];
    const float* W1 = (const float*)d_in[4];
    const float* b1 = (const float*)d_in[5];
    const float* W2 = (const float*)d_in[6];
    const float* b2 = (const float*)d_in[7];

    int n = in_sizes[0] / 128;   // 100000
    int e = in_sizes[1] / 2;     // 1600000

    // CSR build (once; reused by all 3 layers)
    k_zero<<<(n + 255) / 256, 256>>>(n);
    k_hist<<<(e + 255) / 256, 256>>>(ei, e, n);
    k_scan<<<1, 1024>>>(n);
    k_fill<<<(e + 255) / 256, 256>>>(ei, e, n);

    int gemmGrid = (n + 63) / 64;   // RPB = 64
    int aggGrid  = (n + 7) / 8;

    // layer 0
    k_gemm_f2<128, 4, true ><<<gemmGrid, 256>>>(x, W0, n);
    k_agg128<true><<<aggGrid, 256>>>(b0, n);
    // layer 1
    k_gemm_f2<128, 4, false><<<gemmGrid, 256>>>(nullptr, W1, n);
    k_agg128<true><<<aggGrid, 256>>>(b1, n);
    // layer 2 (64 cols, no relu, writes d_out)
    k_gemm_f2<64, 2, false><<<gemmGrid, 256>>>(nullptr, W2, n);
    k_agg64<<<aggGrid, 256>>>(b2, (float*)d_out, n);
}

// round 7
// speedup vs baseline: 1.7908x; 1.3304x over previous
#include <cuda_runtime.h>
#include <cstdint>

#define NMAX 100000
#define EMAX 1600000

// ---------------- device scratch -------------------------------------------
__device__ int   g_cnt[NMAX];
__device__ int   g_cur[NMAX];
__device__ int   g_off[NMAX + 1];
__device__ float g_dinv[NMAX];
__device__ int   g_srcs[EMAX];
__device__ alignas(16) float g_bufA[(size_t)NMAX * 128];
__device__ alignas(16) float g_bufG[(size_t)NMAX * 128];

// ---------------- f32x2 packed FMA helpers ---------------------------------
__device__ __forceinline__ void fma2(unsigned long long& acc, unsigned long long a,
                                     unsigned long long b) {
    asm("fma.rn.f32x2 %0, %1, %2, %0;" : "+l"(acc) : "l"(a), "l"(b));
}
__device__ __forceinline__ unsigned long long splat2(float v) {
    unsigned long long r;
    uint32_t b = __float_as_uint(v);
    asm("mov.b64 %0, {%1, %1};" : "=l"(r) : "r"(b));
    return r;
}
__device__ __forceinline__ float2 unpack2(unsigned long long v) {
    uint32_t lo, hi;
    asm("mov.b64 {%0, %1}, %2;" : "=r"(lo), "=r"(hi) : "l"(v));
    return make_float2(__uint_as_float(lo), __uint_as_float(hi));
}

// ---------------- CSR build ------------------------------------------------
__global__ void k_zero(int n) {
    int i = blockIdx.x * blockDim.x + threadIdx.x;
    if (i < n) { g_cnt[i] = 0; g_cur[i] = 0; }
}
__global__ void k_hist(const int* __restrict__ ei, int e, int n) {
    int i = blockIdx.x * blockDim.x + threadIdx.x;
    if (i < e) {
        int d = ei[e + i];
        if ((unsigned)d < (unsigned)n) atomicAdd(&g_cnt[d], 1);
    }
}
__global__ void k_scan(int n) {
    __shared__ int part[1024];
    int t  = threadIdx.x;
    int ch = (n + 1023) >> 10;
    int b  = t * ch;
    int en = min(n, b + ch);
    int s = 0;
    for (int i = b; i < en; i++) s += g_cnt[i];
    part[t] = s;
    __syncthreads();
    for (int off = 1; off < 1024; off <<= 1) {
        int v = (t >= off) ? part[t - off] : 0;
        __syncthreads();
        part[t] += v;
        __syncthreads();
    }
    int ex = (t == 0) ? 0 : part[t - 1];
    for (int i = b; i < en; i++) {
        g_off[i] = ex;
        int c = g_cnt[i];
        ex += c;
        g_dinv[i] = rsqrtf((float)(c + 1));
    }
    if (t == 1023) g_off[n] = part[1023];
}
__global__ void k_fill(const int* __restrict__ ei, int e, int n) {
    int i = blockIdx.x * blockDim.x + threadIdx.x;
    if (i < e) {
        int d = ei[e + i];
        int s = ei[i];
        if ((unsigned)d < (unsigned)n && (unsigned)s < (unsigned)n) {
            int pos = g_off[d] + atomicAdd(&g_cur[d], 1);
            g_srcs[pos] = s;
        }
    }
}

// ---------------- GEMM: g_bufG = dinv[row] * (X @ W) -----------------------
// R3 structure (tiling, staging, addressing identical); inner math = f32x2.
// X: [n,128], W: [128,NCOL]. 256 threads/block, 4 rows x 4 cols per thread.
template <int NCOL, bool FROM_EXT>
__global__ void __launch_bounds__(256)
k_gemm(const float* __restrict__ Xext, const float* __restrict__ W, int n) {
    constexpr int TX  = NCOL / 4;     // threads across cols (32 / 16)
    constexpr int TY  = 256 / TX;     // row groups (8 / 16)
    constexpr int RPB = 4 * TY;       // rows per block (32 / 64)
    constexpr int KC  = 64;           // k chunk

    __shared__ float Ws[KC * NCOL];   // 32KB / 16KB
    __shared__ float Xs[RPB * 128];   // 16KB / 32KB

    const float4* Xsrc = FROM_EXT ? (const float4*)Xext : (const float4*)g_bufA;

    int tid  = threadIdx.x;
    int row0 = blockIdx.x * RPB;

    // stage X tile (float4)
    for (int i = tid; i < RPB * 32; i += 256) {
        int r = i >> 5, c = i & 31;
        int gr = row0 + r;
        float4 v = (gr < n) ? Xsrc[(size_t)gr * 32 + c]
                            : make_float4(0.f, 0.f, 0.f, 0.f);
        ((float4*)Xs)[i] = v;
    }

    int tx = tid % TX, ty = tid / TX;
    int rbase = ty * 4;

    unsigned long long acc[4][2];   // 4 rows x (2 f32x2 col-pairs)
#pragma unroll
    for (int r = 0; r < 4; r++) { acc[r][0] = 0ull; acc[r][1] = 0ull; }

    for (int kc = 0; kc < 128; kc += KC) {
        __syncthreads();
        for (int i = tid; i < KC * NCOL / 4; i += 256)
            ((float4*)Ws)[i] = ((const float4*)W)[kc * (NCOL / 4) + i];
        __syncthreads();

#pragma unroll 4
        for (int k = 0; k < KC; k += 4) {
            // same 16B LDS.128 addresses as R3 (tx*16B stride, conflict-free)
            ulonglong2 b0 = *(const ulonglong2*)(Ws + (k + 0) * NCOL + tx * 4);
            ulonglong2 b1 = *(const ulonglong2*)(Ws + (k + 1) * NCOL + tx * 4);
            ulonglong2 b2 = *(const ulonglong2*)(Ws + (k + 2) * NCOL + tx * 4);
            ulonglong2 b3 = *(const ulonglong2*)(Ws + (k + 3) * NCOL + tx * 4);
#pragma unroll
            for (int r = 0; r < 4; r++) {
                float4 a = ((float4*)Xs)[(rbase + r) * 32 + ((kc + k) >> 2)];
                unsigned long long a0 = splat2(a.x);
                fma2(acc[r][0], a0, b0.x); fma2(acc[r][1], a0, b0.y);
                unsigned long long a1 = splat2(a.y);
                fma2(acc[r][0], a1, b1.x); fma2(acc[r][1], a1, b1.y);
                unsigned long long a2 = splat2(a.z);
                fma2(acc[r][0], a2, b2.x); fma2(acc[r][1], a2, b2.y);
                unsigned long long a3 = splat2(a.w);
                fma2(acc[r][0], a3, b3.x); fma2(acc[r][1], a3, b3.y);
            }
        }
    }

#pragma unroll
    for (int r = 0; r < 4; r++) {
        int gr = row0 + rbase + r;
        if (gr < n) {
            float dv = g_dinv[gr];
            float2 p0 = unpack2(acc[r][0]);
            float2 p1 = unpack2(acc[r][1]);
            float4 o = make_float4(p0.x * dv, p0.y * dv, p1.x * dv, p1.y * dv);
            ((float4*)g_bufG)[(size_t)gr * (NCOL / 4) + tx] = o;
        }
    }
}

// ------- Aggregation: out[d] = act(dinv[d]*(G[d] + sum_s G[s]) + b) --------
template <bool RELU>
__global__ void k_agg128(const float* __restrict__ bias, int n) {
    int w = (blockIdx.x * blockDim.x + threadIdx.x) >> 5;
    if (w >= n) return;
    int lane = threadIdx.x & 31;
    const float4* G = (const float4*)g_bufG;

    float4 acc = G[(size_t)w * 32 + lane];
    int beg = g_off[w], end = g_off[w + 1];
    int i = beg;
    for (; i + 2 <= end; i += 2) {
        int s0 = g_srcs[i], s1 = g_srcs[i + 1];
        float4 v0 = G[(size_t)s0 * 32 + lane];
        float4 v1 = G[(size_t)s1 * 32 + lane];
        acc.x += v0.x + v1.x; acc.y += v0.y + v1.y;
        acc.z += v0.z + v1.z; acc.w += v0.w + v1.w;
    }
    if (i < end) {
        int s = g_srcs[i];
        float4 v = G[(size_t)s * 32 + lane];
        acc.x += v.x; acc.y += v.y; acc.z += v.z; acc.w += v.w;
    }
    float dv = g_dinv[w];
    float4 bb = ((const float4*)bias)[lane];
    float4 o = make_float4(acc.x * dv + bb.x, acc.y * dv + bb.y,
                           acc.z * dv + bb.z, acc.w * dv + bb.w);
    if (RELU) {
        o.x = fmaxf(o.x, 0.f); o.y = fmaxf(o.y, 0.f);
        o.z = fmaxf(o.z, 0.f); o.w = fmaxf(o.w, 0.f);
    }
    ((float4*)g_bufA)[(size_t)w * 32 + lane] = o;
}

__global__ void k_agg64(const float* __restrict__ bias, float* __restrict__ O, int n) {
    int w = (blockIdx.x * blockDim.x + threadIdx.x) >> 5;
    if (w >= n) return;
    int lane = threadIdx.x & 31;
    const float2* G = (const float2*)g_bufG;

    float2 acc = G[(size_t)w * 32 + lane];
    int beg = g_off[w], end = g_off[w + 1];
    int i = beg;
    for (; i + 2 <= end; i += 2) {
        int s0 = g_srcs[i], s1 = g_srcs[i + 1];
        float2 v0 = G[(size_t)s0 * 32 + lane];
        float2 v1 = G[(size_t)s1 * 32 + lane];
        acc.x += v0.x + v1.x; acc.y += v0.y + v1.y;
    }
    if (i < end) {
        int s = g_srcs[i];
        float2 v = G[(size_t)s * 32 + lane];
        acc.x += v.x; acc.y += v.y;
    }
    float dv = g_dinv[w];
    float2 bb = ((const float2*)bias)[lane];
    float2 o = make_float2(acc.x * dv + bb.x, acc.y * dv + bb.y);
    ((float2*)O)[(size_t)w * 32 + lane] = o;
}

// ---------------- launch ----------------------------------------------------
extern "C" void kernel_launch(void* const* d_in, const int* in_sizes, int n_in,
                              void* d_out, int out_size) {
    const float* x  = (const float*)d_in[0];
    const int*   ei = (const int*)d_in[1];
    const float* W0 = (const float*)d_in[2];
    const float* b0 = (const float*)d_in[3];
    const float* W1 = (const float*)d_in[4];
    const float* b1 = (const float*)d_in[5];
    const float* W2 = (const float*)d_in[6];
    const float* b2 = (const float*)d_in[7];

    int n = in_sizes[0] / 128;   // 100000
    int e = in_sizes[1] / 2;     // 1600000

    // CSR build (once; reused by all 3 layers)
    k_zero<<<(n + 255) / 256, 256>>>(n);
    k_hist<<<(e + 255) / 256, 256>>>(ei, e, n);
    k_scan<<<1, 1024>>>(n);
    k_fill<<<(e + 255) / 256, 256>>>(ei, e, n);

    int aggGrid = (n + 7) / 8;  // 8 warps/block

    // layer 0
    k_gemm<128, true ><<<(n + 31) / 32, 256>>>(x, W0, n);
    k_agg128<true><<<aggGrid, 256>>>(b0, n);
    // layer 1
    k_gemm<128, false><<<(n + 31) / 32, 256>>>(nullptr, W1, n);
    k_agg128<true><<<aggGrid, 256>>>(b1, n);
    // layer 2 (64 cols, no relu, writes d_out)
    k_gemm<64, false><<<(n + 63) / 64, 256>>>(nullptr, W2, n);
    k_agg64<<<aggGrid, 256>>>(b2, (float*)d_out, n);
}

// round 8
// speedup vs baseline: 1.9502x; 1.0890x over previous
#include <cuda_runtime.h>
#include <cuda_fp16.h>
#include <cstdint>

#define NMAX 100000
#define EMAX 1600000

// ---------------- device scratch -------------------------------------------
__device__ int   g_cnt[NMAX];
__device__ int   g_cur[NMAX];
__device__ int   g_off[NMAX + 1];
__device__ float g_dinv[NMAX];
__device__ int   g_srcs[EMAX];
__device__ alignas(16) float  g_bufA[(size_t)NMAX * 128];   // fp32 activations
__device__ alignas(16) __half g_bufG[(size_t)NMAX * 128];   // fp16 gather buffer

// ---------------- f32x2 packed FMA helpers ---------------------------------
__device__ __forceinline__ void fma2(unsigned long long& acc, unsigned long long a,
                                     unsigned long long b) {
    asm("fma.rn.f32x2 %0, %1, %2, %0;" : "+l"(acc) : "l"(a), "l"(b));
}
__device__ __forceinline__ unsigned long long splat2(float v) {
    unsigned long long r;
    uint32_t b = __float_as_uint(v);
    asm("mov.b64 %0, {%1, %1};" : "=l"(r) : "r"(b));
    return r;
}
__device__ __forceinline__ float2 unpack2(unsigned long long v) {
    uint32_t lo, hi;
    asm("mov.b64 {%0, %1}, %2;" : "=r"(lo), "=r"(hi) : "l"(v));
    return make_float2(__uint_as_float(lo), __uint_as_float(hi));
}

// ---------------- CSR build ------------------------------------------------
__global__ void k_zero(int n) {
    int i = blockIdx.x * blockDim.x + threadIdx.x;
    if (i < n) { g_cnt[i] = 0; g_cur[i] = 0; }
}
__global__ void k_hist(const int* __restrict__ ei, int e, int n) {
    int i = blockIdx.x * blockDim.x + threadIdx.x;
    if (i < e) {
        int d = ei[e + i];
        if ((unsigned)d < (unsigned)n) atomicAdd(&g_cnt[d], 1);
    }
}
__global__ void k_scan(int n) {
    __shared__ int part[1024];
    int t  = threadIdx.x;
    int ch = (n + 1023) >> 10;
    int b  = t * ch;
    int en = min(n, b + ch);
    int s = 0;
    for (int i = b; i < en; i++) s += g_cnt[i];
    part[t] = s;
    __syncthreads();
    for (int off = 1; off < 1024; off <<= 1) {
        int v = (t >= off) ? part[t - off] : 0;
        __syncthreads();
        part[t] += v;
        __syncthreads();
    }
    int ex = (t == 0) ? 0 : part[t - 1];
    for (int i = b; i < en; i++) {
        g_off[i] = ex;
        int c = g_cnt[i];
        ex += c;
        g_dinv[i] = rsqrtf((float)(c + 1));
    }
    if (t == 1023) g_off[n] = part[1023];
}
__global__ void k_fill(const int* __restrict__ ei, int e, int n) {
    int i = blockIdx.x * blockDim.x + threadIdx.x;
    if (i < e) {
        int d = ei[e + i];
        int s = ei[i];
        if ((unsigned)d < (unsigned)n && (unsigned)s < (unsigned)n) {
            int pos = g_off[d] + atomicAdd(&g_cur[d], 1);
            g_srcs[pos] = s;
        }
    }
}

// ---------------- GEMM: g_bufG = fp16( dinv[row] * (X @ W) ) ---------------
// R7 structure unchanged; epilogue converts to fp16.
template <int NCOL, bool FROM_EXT>
__global__ void __launch_bounds__(256)
k_gemm(const float* __restrict__ Xext, const float* __restrict__ W, int n) {
    constexpr int TX  = NCOL / 4;     // threads across cols (32 / 16)
    constexpr int TY  = 256 / TX;     // row groups (8 / 16)
    constexpr int RPB = 4 * TY;       // rows per block (32 / 64)
    constexpr int KC  = 64;           // k chunk

    __shared__ float Ws[KC * NCOL];   // 32KB / 16KB
    __shared__ float Xs[RPB * 128];   // 16KB / 32KB

    const float4* Xsrc = FROM_EXT ? (const float4*)Xext : (const float4*)g_bufA;

    int tid  = threadIdx.x;
    int row0 = blockIdx.x * RPB;

    // stage X tile (float4)
    for (int i = tid; i < RPB * 32; i += 256) {
        int r = i >> 5, c = i & 31;
        int gr = row0 + r;
        float4 v = (gr < n) ? Xsrc[(size_t)gr * 32 + c]
                            : make_float4(0.f, 0.f, 0.f, 0.f);
        ((float4*)Xs)[i] = v;
    }

    int tx = tid % TX, ty = tid / TX;
    int rbase = ty * 4;

    unsigned long long acc[4][2];   // 4 rows x (2 f32x2 col-pairs)
#pragma unroll
    for (int r = 0; r < 4; r++) { acc[r][0] = 0ull; acc[r][1] = 0ull; }

    for (int kc = 0; kc < 128; kc += KC) {
        __syncthreads();
        for (int i = tid; i < KC * NCOL / 4; i += 256)
            ((float4*)Ws)[i] = ((const float4*)W)[kc * (NCOL / 4) + i];
        __syncthreads();

#pragma unroll 4
        for (int k = 0; k < KC; k += 4) {
            ulonglong2 b0 = *(const ulonglong2*)(Ws + (k + 0) * NCOL + tx * 4);
            ulonglong2 b1 = *(const ulonglong2*)(Ws + (k + 1) * NCOL + tx * 4);
            ulonglong2 b2 = *(const ulonglong2*)(Ws + (k + 2) * NCOL + tx * 4);
            ulonglong2 b3 = *(const ulonglong2*)(Ws + (k + 3) * NCOL + tx * 4);
#pragma unroll
            for (int r = 0; r < 4; r++) {
                float4 a = ((float4*)Xs)[(rbase + r) * 32 + ((kc + k) >> 2)];
                unsigned long long a0 = splat2(a.x);
                fma2(acc[r][0], a0, b0.x); fma2(acc[r][1], a0, b0.y);
                unsigned long long a1 = splat2(a.y);
                fma2(acc[r][0], a1, b1.x); fma2(acc[r][1], a1, b1.y);
                unsigned long long a2 = splat2(a.z);
                fma2(acc[r][0], a2, b2.x); fma2(acc[r][1], a2, b2.y);
                unsigned long long a3 = splat2(a.w);
                fma2(acc[r][0], a3, b3.x); fma2(acc[r][1], a3, b3.y);
            }
        }
    }

#pragma unroll
    for (int r = 0; r < 4; r++) {
        int gr = row0 + rbase + r;
        if (gr < n) {
            float dv = g_dinv[gr];
            float2 p0 = unpack2(acc[r][0]);
            float2 p1 = unpack2(acc[r][1]);
            half2 h01 = __floats2half2_rn(p0.x * dv, p0.y * dv);
            half2 h23 = __floats2half2_rn(p1.x * dv, p1.y * dv);
            uint2 packed = make_uint2(*(uint32_t*)&h01, *(uint32_t*)&h23);
            // 4 halves = 8 bytes per thread at col tx*4
            *(uint2*)(g_bufG + (size_t)gr * NCOL + tx * 4) = packed;
        }
    }
}

// ------- Aggregation: out[d] = act(dinv[d]*(G[d] + sum_s G[s]) + b) --------
// G is fp16; accumulate fp32. 128-col layers write fp32 g_bufA.
template <bool RELU>
__global__ void k_agg128(const float* __restrict__ bias, int n) {
    int w = (blockIdx.x * blockDim.x + threadIdx.x) >> 5;
    if (w >= n) return;
    int lane = threadIdx.x & 31;
    const uint2* G = (const uint2*)g_bufG;   // 4 halves per uint2

    float4 acc;
    {
        uint2 u = G[(size_t)w * 32 + lane];  // self loop
        float2 f01 = __half22float2(*(half2*)&u.x);
        float2 f23 = __half22float2(*(half2*)&u.y);
        acc = make_float4(f01.x, f01.y, f23.x, f23.y);
    }
    int beg = g_off[w], end = g_off[w + 1];
    int i = beg;
    for (; i + 2 <= end; i += 2) {
        int s0 = g_srcs[i], s1 = g_srcs[i + 1];
        uint2 u0 = G[(size_t)s0 * 32 + lane];
        uint2 u1 = G[(size_t)s1 * 32 + lane];
        float2 a01 = __half22float2(*(half2*)&u0.x);
        float2 a23 = __half22float2(*(half2*)&u0.y);
        float2 b01 = __half22float2(*(half2*)&u1.x);
        float2 b23 = __half22float2(*(half2*)&u1.y);
        acc.x += a01.x + b01.x; acc.y += a01.y + b01.y;
        acc.z += a23.x + b23.x; acc.w += a23.y + b23.y;
    }
    if (i < end) {
        int s = g_srcs[i];
        uint2 u = G[(size_t)s * 32 + lane];
        float2 f01 = __half22float2(*(half2*)&u.x);
        float2 f23 = __half22float2(*(half2*)&u.y);
        acc.x += f01.x; acc.y += f01.y; acc.z += f23.x; acc.w += f23.y;
    }
    float dv = g_dinv[w];
    float4 bb = ((const float4*)bias)[lane];
    float4 o = make_float4(acc.x * dv + bb.x, acc.y * dv + bb.y,
                           acc.z * dv + bb.z, acc.w * dv + bb.w);
    if (RELU) {
        o.x = fmaxf(o.x, 0.f); o.y = fmaxf(o.y, 0.f);
        o.z = fmaxf(o.z, 0.f); o.w = fmaxf(o.w, 0.f);
    }
    ((float4*)g_bufA)[(size_t)w * 32 + lane] = o;
}

// 64-col final layer: G fp16, writes external fp32 output, no relu.
__global__ void k_agg64(const float* __restrict__ bias, float* __restrict__ O, int n) {
    int w = (blockIdx.x * blockDim.x + threadIdx.x) >> 5;
    if (w >= n) return;
    int lane = threadIdx.x & 31;
    const uint32_t* G = (const uint32_t*)g_bufG;  // 2 halves per uint

    float2 acc;
    {
        uint32_t u = G[(size_t)w * 32 + lane];
        acc = __half22float2(*(half2*)&u);
    }
    int beg = g_off[w], end = g_off[w + 1];
    int i = beg;
    for (; i + 2 <= end; i += 2) {
        int s0 = g_srcs[i], s1 = g_srcs[i + 1];
        uint32_t u0 = G[(size_t)s0 * 32 + lane];
        uint32_t u1 = G[(size_t)s1 * 32 + lane];
        float2 a = __half22float2(*(half2*)&u0);
        float2 b = __half22float2(*(half2*)&u1);
        acc.x += a.x + b.x; acc.y += a.y + b.y;
    }
    if (i < end) {
        int s = g_srcs[i];
        uint32_t u = G[(size_t)s * 32 + lane];
        float2 f = __half22float2(*(half2*)&u);
        acc.x += f.x; acc.y += f.y;
    }
    float dv = g_dinv[w];
    float2 bb = ((const float2*)bias)[lane];
    float2 o = make_float2(acc.x * dv + bb.x, acc.y * dv + bb.y);
    ((float2*)O)[(size_t)w * 32 + lane] = o;
}

// ---------------- launch ----------------------------------------------------
extern "C" void kernel_launch(void* const* d_in, const int* in_sizes, int n_in,
                              void* d_out, int out_size) {
    const float* x  = (const float*)d_in[0];
    const int*   ei = (const int*)d_in[1];
    const float* W0 = (const float*)d_in[2];
    const float* b0 = (const float*)d_in[3];
    const float* W1 = (const float*)d_in[4];
    const float* b1 = (const float*)d_in[5];
    const float* W2 = (const float*)d_in[6];
    const float* b2 = (const float*)d_in[7];

    int n = in_sizes[0] / 128;   // 100000
    int e = in_sizes[1] / 2;     // 1600000

    // CSR build (once; reused by all 3 layers)
    k_zero<<<(n + 255) / 256, 256>>>(n);
    k_hist<<<(e + 255) / 256, 256>>>(ei, e, n);
    k_scan<<<1, 1024>>>(n);
    k_fill<<<(e + 255) / 256, 256>>>(ei, e, n);

    int aggGrid = (n + 7) / 8;  // 8 warps/block

    // layer 0
    k_gemm<128, true ><<<(n + 31) / 32, 256>>>(x, W0, n);
    k_agg128<true><<<aggGrid, 256>>>(b0, n);
    // layer 1
    k_gemm<128, false><<<(n + 31) / 32, 256>>>(nullptr, W1, n);
    k_agg128<true><<<aggGrid, 256>>>(b1, n);
    // layer 2 (64 cols, no relu, writes d_out)
    k_gemm<64, false><<<(n + 63) / 64, 256>>>(nullptr, W2, n);
    k_agg64<<<aggGrid, 256>>>(b2, (float*)d_out, n);
}